// round 1
// baseline (speedup 1.0000x reference)
#include <cuda_runtime.h>
#include <cuda_bf16.h>
#include <math.h>

#define BDIM 512
#define DDIM 512
#define CDIM 100000
#define SCALE_F 64.0f
#define MARGIN_F 0.35f

#define BM 64
#define BN 128
#define BK 32
#define NCHUNK ((CDIM + BN - 1) / BN)   // 782

// ---------------- device scratch (static, allowed) ----------------
__device__ __nv_bfloat16 g_xb[BDIM * DDIM];          // normalized x, bf16
__device__ float         g_xn[BDIM * DDIM];          // normalized x, fp32
__device__ __nv_bfloat16 g_wb[(size_t)CDIM * DDIM];  // normalized wt, bf16 (~102 MB)
__device__ float         g_pm[BDIM * NCHUNK];        // per-chunk row max
__device__ float         g_ps[BDIM * NCHUNK];        // per-chunk row sumexp
__device__ float         g_cosgt[BDIM];
__device__ float         g_nll[BDIM];
__device__ int           g_is64;

// ---------------- gt dtype detection ----------------
// If gt is int64, the odd 32-bit words of the first 512 words are all zero
// (values in [0,1e5), nonnegative). If int32 (512 words total), odd words are
// random gt values — essentially never all zero.
__global__ void detect_gt_kernel(const int* __restrict__ graw) {
    __shared__ int any_nz;
    if (threadIdx.x == 0) any_nz = 0;
    __syncthreads();
    if ((threadIdx.x & 1) && graw[threadIdx.x] != 0) any_nz = 1;
    __syncthreads();
    if (threadIdx.x == 0) g_is64 = any_nz ? 0 : 1;
}

// ---------------- normalize x ----------------
__global__ void __launch_bounds__(128) norm_x_kernel(const float* __restrict__ x) {
    int b = blockIdx.x, tid = threadIdx.x;
    float4 v = ((const float4*)(x + (size_t)b * DDIM))[tid];
    float ss = v.x*v.x + v.y*v.y + v.z*v.z + v.w*v.w;
    #pragma unroll
    for (int o = 16; o; o >>= 1) ss += __shfl_xor_sync(0xffffffffu, ss, o);
    __shared__ float sm[4];
    if ((tid & 31) == 0) sm[tid >> 5] = ss;
    __syncthreads();
    float tot = sm[0] + sm[1] + sm[2] + sm[3];
    float r = 1.0f / fmaxf(sqrtf(tot), 1e-12f);
    float4 n = make_float4(v.x*r, v.y*r, v.z*r, v.w*r);
    ((float4*)(g_xn + (size_t)b * DDIM))[tid] = n;
    __nv_bfloat162 p0 = __floats2bfloat162_rn(n.x, n.y);
    __nv_bfloat162 p1 = __floats2bfloat162_rn(n.z, n.w);
    __nv_bfloat162* dst = (__nv_bfloat162*)(g_xb + (size_t)b * DDIM);
    dst[tid * 2 + 0] = p0;
    dst[tid * 2 + 1] = p1;
}

// ---------------- normalize wt -> bf16 ----------------
__global__ void __launch_bounds__(128) norm_w_kernel(const float* __restrict__ wt) {
    int c = blockIdx.x, tid = threadIdx.x;
    float4 v = ((const float4*)(wt + (size_t)c * DDIM))[tid];
    float ss = v.x*v.x + v.y*v.y + v.z*v.z + v.w*v.w;
    #pragma unroll
    for (int o = 16; o; o >>= 1) ss += __shfl_xor_sync(0xffffffffu, ss, o);
    __shared__ float sm[4];
    if ((tid & 31) == 0) sm[tid >> 5] = ss;
    __syncthreads();
    float tot = sm[0] + sm[1] + sm[2] + sm[3];
    float r = 1.0f / fmaxf(sqrtf(tot), 1e-12f);
    __nv_bfloat162 p0 = __floats2bfloat162_rn(v.x*r, v.y*r);
    __nv_bfloat162 p1 = __floats2bfloat162_rn(v.z*r, v.w*r);
    __nv_bfloat162* dst = (__nv_bfloat162*)(g_wb + (size_t)c * DDIM);
    dst[tid * 2 + 0] = p0;
    dst[tid * 2 + 1] = p1;
}

// ---------------- exact fp32 cos at target class ----------------
__global__ void __launch_bounds__(128) cosgt_kernel(const void* __restrict__ gt,
                                                    const float* __restrict__ wt) {
    int b = blockIdx.x, tid = threadIdx.x;
    long long c = g_is64 ? ((const long long*)gt)[b] : (long long)((const int*)gt)[b];
    float4 w  = ((const float4*)(wt + (size_t)c * DDIM))[tid];
    float4 xn = ((const float4*)(g_xn + (size_t)b * DDIM))[tid];
    float ss = w.x*w.x + w.y*w.y + w.z*w.z + w.w*w.w;
    float dp = w.x*xn.x + w.y*xn.y + w.z*xn.z + w.w*xn.w;
    #pragma unroll
    for (int o = 16; o; o >>= 1) {
        ss += __shfl_xor_sync(0xffffffffu, ss, o);
        dp += __shfl_xor_sync(0xffffffffu, dp, o);
    }
    __shared__ float sms[4], smd[4];
    if ((tid & 31) == 0) { sms[tid >> 5] = ss; smd[tid >> 5] = dp; }
    __syncthreads();
    if (tid == 0) {
        float tss = sms[0] + sms[1] + sms[2] + sms[3];
        float tdp = smd[0] + smd[1] + smd[2] + smd[3];
        g_cosgt[b] = tdp / fmaxf(sqrtf(tss), 1e-12f);
    }
}

// ---------------- GEMM + fused online-softmax partials ----------------
#define ASTRIDE (BK + 8)
__global__ void __launch_bounds__(256) gemm_softmax_kernel() {
    __shared__ __nv_bfloat16 As[BM][ASTRIDE];
    __shared__ __nv_bfloat16 Bs[BN][ASTRIDE];
    __shared__ float         red[BM][4];

    int tid  = threadIdx.x;
    int lane = tid & 31;
    int warp = tid >> 5;
    int wm = warp >> 2;       // 0..1
    int wn = warp & 3;        // 0..3
    int m0 = blockIdx.y * BM;
    int n0 = blockIdx.x * BN;

    float acc[2][4][4];
    #pragma unroll
    for (int i = 0; i < 2; i++)
        #pragma unroll
        for (int j = 0; j < 4; j++)
            #pragma unroll
            for (int e = 0; e < 4; e++) acc[i][j][e] = 0.0f;

    for (int k0 = 0; k0 < DDIM; k0 += BK) {
        // A tile: 64 rows x 32 cols bf16; 256 threads x 8 elems
        {
            int row = tid >> 2, cg = tid & 3;
            uint4 v = *(const uint4*)(g_xb + (size_t)(m0 + row) * DDIM + k0 + cg * 8);
            *(uint4*)(&As[row][cg * 8]) = v;
        }
        // B tile: 128 rows x 32 cols bf16; 512 uint4, 2 per thread
        #pragma unroll
        for (int it = 0; it < 2; it++) {
            int idx = tid + it * 256;
            int row = idx >> 2, q = idx & 3;
            int gn = n0 + row;
            uint4 v = make_uint4(0u, 0u, 0u, 0u);
            if (gn < CDIM) v = *(const uint4*)(g_wb + (size_t)gn * DDIM + k0 + q * 8);
            *(uint4*)(&Bs[row][q * 8]) = v;
        }
        __syncthreads();

        #pragma unroll
        for (int kk = 0; kk < BK; kk += 16) {
            unsigned a[2][4];
            #pragma unroll
            for (int i = 0; i < 2; i++) {
                int r   = wm * 32 + i * 16 + (lane & 15);
                int col = kk + ((lane >> 4) << 3);
                unsigned addr = (unsigned)__cvta_generic_to_shared(&As[r][col]);
                asm volatile("ldmatrix.sync.aligned.m8n8.x4.shared.b16 {%0,%1,%2,%3}, [%4];"
                             : "=r"(a[i][0]), "=r"(a[i][1]), "=r"(a[i][2]), "=r"(a[i][3])
                             : "r"(addr));
            }
            unsigned bfr[4][2];
            #pragma unroll
            for (int j2 = 0; j2 < 2; j2++) {
                int nrow = wn * 32 + j2 * 16 + (lane & 7) + ((lane >> 4) << 3);
                int col  = kk + (((lane >> 3) & 1) << 3);
                unsigned addr = (unsigned)__cvta_generic_to_shared(&Bs[nrow][col]);
                unsigned r0, r1, r2, r3;
                asm volatile("ldmatrix.sync.aligned.m8n8.x4.shared.b16 {%0,%1,%2,%3}, [%4];"
                             : "=r"(r0), "=r"(r1), "=r"(r2), "=r"(r3) : "r"(addr));
                bfr[j2 * 2 + 0][0] = r0; bfr[j2 * 2 + 0][1] = r1;
                bfr[j2 * 2 + 1][0] = r2; bfr[j2 * 2 + 1][1] = r3;
            }
            #pragma unroll
            for (int i = 0; i < 2; i++)
                #pragma unroll
                for (int j = 0; j < 4; j++)
                    asm volatile(
                        "mma.sync.aligned.m16n8k16.row.col.f32.bf16.bf16.f32 "
                        "{%0,%1,%2,%3},{%4,%5,%6,%7},{%8,%9},{%0,%1,%2,%3};"
                        : "+f"(acc[i][j][0]), "+f"(acc[i][j][1]),
                          "+f"(acc[i][j][2]), "+f"(acc[i][j][3])
                        : "r"(a[i][0]), "r"(a[i][1]), "r"(a[i][2]), "r"(a[i][3]),
                          "r"(bfr[j][0]), "r"(bfr[j][1]));
        }
        __syncthreads();
    }

    // ---- fused online-softmax epilogue: per-row (max, sumexp) over this BN chunk ----
    int g4 = lane >> 2;   // 0..7
    int t4 = lane & 3;    // 0..3

    float rmax[4];
    #pragma unroll
    for (int i = 0; i < 2; i++) {
        #pragma unroll
        for (int h = 0; h < 2; h++) {
            float m = -INFINITY;
            #pragma unroll
            for (int j = 0; j < 4; j++) {
                #pragma unroll
                for (int e2 = 0; e2 < 2; e2++) {
                    int gc = n0 + wn * 32 + j * 8 + t4 * 2 + e2;
                    float z = (gc < CDIM) ? SCALE_F * acc[i][j][h * 2 + e2] : -INFINITY;
                    m = fmaxf(m, z);
                }
            }
            m = fmaxf(m, __shfl_xor_sync(0xffffffffu, m, 1));
            m = fmaxf(m, __shfl_xor_sync(0xffffffffu, m, 2));
            rmax[i * 2 + h] = m;
        }
    }
    if (t4 == 0) {
        #pragma unroll
        for (int i = 0; i < 2; i++)
            #pragma unroll
            for (int h = 0; h < 2; h++) {
                int r = wm * 32 + i * 16 + h * 8 + g4;
                red[r][wn] = rmax[i * 2 + h];
            }
    }
    __syncthreads();
    float fmx[4];
    #pragma unroll
    for (int i = 0; i < 2; i++)
        #pragma unroll
        for (int h = 0; h < 2; h++) {
            int r = wm * 32 + i * 16 + h * 8 + g4;
            fmx[i * 2 + h] = fmaxf(fmaxf(red[r][0], red[r][1]),
                                   fmaxf(red[r][2], red[r][3]));
        }
    __syncthreads();

    float rsum[4];
    #pragma unroll
    for (int i = 0; i < 2; i++) {
        #pragma unroll
        for (int h = 0; h < 2; h++) {
            float s = 0.0f;
            #pragma unroll
            for (int j = 0; j < 4; j++) {
                #pragma unroll
                for (int e2 = 0; e2 < 2; e2++) {
                    int gc = n0 + wn * 32 + j * 8 + t4 * 2 + e2;
                    if (gc < CDIM)
                        s += expf(SCALE_F * acc[i][j][h * 2 + e2] - fmx[i * 2 + h]);
                }
            }
            s += __shfl_xor_sync(0xffffffffu, s, 1);
            s += __shfl_xor_sync(0xffffffffu, s, 2);
            rsum[i * 2 + h] = s;
        }
    }
    if (t4 == 0) {
        #pragma unroll
        for (int i = 0; i < 2; i++)
            #pragma unroll
            for (int h = 0; h < 2; h++) {
                int r = wm * 32 + i * 16 + h * 8 + g4;
                red[r][wn] = rsum[i * 2 + h];
            }
    }
    __syncthreads();
    if (wn == 0 && t4 == 0) {
        #pragma unroll
        for (int i = 0; i < 2; i++)
            #pragma unroll
            for (int h = 0; h < 2; h++) {
                int r = wm * 32 + i * 16 + h * 8 + g4;
                float S = red[r][0] + red[r][1] + red[r][2] + red[r][3];
                int gb = m0 + r;
                g_pm[gb * NCHUNK + blockIdx.x] = fmx[i * 2 + h];
                g_ps[gb * NCHUNK + blockIdx.x] = S;
            }
    }
}

// ---------------- per-row logsumexp merge + margin + NLL ----------------
__global__ void __launch_bounds__(256) reduce_kernel() {
    int b = blockIdx.x, tid = threadIdx.x;
    float M = -INFINITY, S = 0.0f;
    for (int i = tid; i < NCHUNK; i += 256) {
        float m = g_pm[b * NCHUNK + i];
        float s = g_ps[b * NCHUNK + i];
        if (m > M) { S = S * expf(M - m) + s; M = m; }
        else       { S += s * expf(m - M); }
    }
    __shared__ float sm[256], ss[256];
    sm[tid] = M; ss[tid] = S;
    __syncthreads();
    for (int o = 128; o; o >>= 1) {
        if (tid < o) {
            float m2 = sm[tid + o], s2 = ss[tid + o];
            float m1 = sm[tid],     s1 = ss[tid];
            float mn = fmaxf(m1, m2);
            sm[tid] = mn;
            ss[tid] = s1 * expf(m1 - mn) + s2 * expf(m2 - mn);
        }
        __syncthreads();
    }
    if (tid == 0) {
        float Mf = sm[0], Sf = ss[0];
        float zg = SCALE_F * g_cosgt[b];
        float zm = zg - SCALE_F * MARGIN_F;
        // replace the unmargined gt term with the margined one
        Sf = Sf - expf(zg - Mf) + expf(zm - Mf);
        float lse = Mf + logf(Sf);
        g_nll[b] = lse - zm;
    }
}

__global__ void __launch_bounds__(512) mean_kernel(float* __restrict__ out) {
    __shared__ float sm[512];
    int t = threadIdx.x;
    sm[t] = g_nll[t];
    __syncthreads();
    for (int o = 256; o; o >>= 1) {
        if (t < o) sm[t] += sm[t + o];
        __syncthreads();
    }
    if (t == 0) out[0] = sm[0] * (1.0f / (float)BDIM);
}

// ---------------- launch ----------------
extern "C" void kernel_launch(void* const* d_in, const int* in_sizes, int n_in,
                              void* d_out, int out_size) {
    const float* x  = (const float*)d_in[0];
    const void*  gt = d_in[1];
    const float* wt = (const float*)d_in[2];
    float* out = (float*)d_out;

    detect_gt_kernel<<<1, 512>>>((const int*)gt);
    norm_x_kernel<<<BDIM, 128>>>(x);
    norm_w_kernel<<<CDIM, 128>>>(wt);
    cosgt_kernel<<<BDIM, 128>>>(gt, wt);
    gemm_softmax_kernel<<<dim3(NCHUNK, BDIM / BM), 256>>>();
    reduce_kernel<<<BDIM, 256>>>();
    mean_kernel<<<1, 512>>>(out);
}

// round 3
// speedup vs baseline: 1.4140x; 1.4140x over previous
#include <cuda_runtime.h>
#include <cuda_bf16.h>
#include <math.h>

#define BDIM 512
#define DDIM 512
#define CDIM 100000
#define SCALE_F 64.0f
#define MARGIN_F 0.35f

#define TILE_N 128
#define NT 782                         // ceil(100000/128)
#define C_PAD (NT * TILE_N)            // padded W rows (zero-filled)
#define NCHUNK NT
#define GRIDX 37                       // 37*4 = 148 CTAs = 1 wave

#define BK 64
#define ASTRIDE_B 1040                 // A smem row stride, bytes (512*2 + 16)
#define BSTRIDE_B 144                  // B smem row stride, bytes (64*2 + 16)
#define A_SMEM_BYTES (128 * ASTRIDE_B)             // 133120
#define B_STAGE_BYTES (128 * BSTRIDE_B)            // 18432
#define OFF_B A_SMEM_BYTES
#define OFF_RED (A_SMEM_BYTES + 2 * B_STAGE_BYTES) // 169984
#define SMEM_DYN (OFF_RED + 128 * 4 * 4)           // 172032

// ---------------- device scratch ----------------
__device__ __nv_bfloat16 g_xb[BDIM * DDIM];
__device__ float         g_xn[BDIM * DDIM];
__device__ __nv_bfloat16 g_wb[(size_t)C_PAD * DDIM];   // ~102.5 MB
__device__ float         g_pm[BDIM * NCHUNK];
__device__ float         g_ps[BDIM * NCHUNK];
__device__ float         g_cosgt[BDIM];
__device__ float         g_nll[BDIM];
__device__ int           g_is64;

// ---------------- helpers ----------------
__device__ __forceinline__ unsigned smem_u32(const void* p) {
    unsigned a;
    asm("{ .reg .u64 t; cvta.to.shared.u64 t, %1; cvt.u32.u64 %0, t; }" : "=r"(a) : "l"(p));
    return a;
}
#define CP_ASYNC16(d, s) asm volatile("cp.async.cg.shared.global [%0], [%1], 16;" :: "r"(d), "l"(s) : "memory")
#define CP_COMMIT()  asm volatile("cp.async.commit_group;" ::: "memory")
#define CP_WAIT1()   asm volatile("cp.async.wait_group 1;" ::: "memory")
#define CP_WAIT0()   asm volatile("cp.async.wait_group 0;" ::: "memory")

// ---------------- small kernels ----------------
__global__ void detect_gt_kernel(const int* __restrict__ graw) {
    __shared__ int any_nz;
    if (threadIdx.x == 0) any_nz = 0;
    __syncthreads();
    if ((threadIdx.x & 1) && graw[threadIdx.x] != 0) any_nz = 1;
    __syncthreads();
    if (threadIdx.x == 0) g_is64 = any_nz ? 0 : 1;
}

__global__ void __launch_bounds__(128) norm_x_kernel(const float* __restrict__ x) {
    int b = blockIdx.x, tid = threadIdx.x;
    float4 v = ((const float4*)(x + (size_t)b * DDIM))[tid];
    float ss = v.x*v.x + v.y*v.y + v.z*v.z + v.w*v.w;
    #pragma unroll
    for (int o = 16; o; o >>= 1) ss += __shfl_xor_sync(0xffffffffu, ss, o);
    __shared__ float sm[4];
    if ((tid & 31) == 0) sm[tid >> 5] = ss;
    __syncthreads();
    float tot = sm[0] + sm[1] + sm[2] + sm[3];
    float r = 1.0f / fmaxf(sqrtf(tot), 1e-12f);
    float4 n = make_float4(v.x*r, v.y*r, v.z*r, v.w*r);
    ((float4*)(g_xn + (size_t)b * DDIM))[tid] = n;
    __nv_bfloat162* dst = (__nv_bfloat162*)(g_xb + (size_t)b * DDIM);
    dst[tid * 2 + 0] = __floats2bfloat162_rn(n.x, n.y);
    dst[tid * 2 + 1] = __floats2bfloat162_rn(n.z, n.w);
}

__global__ void __launch_bounds__(128) norm_w_kernel(const float* __restrict__ wt) {
    int c = blockIdx.x, tid = threadIdx.x;
    __nv_bfloat162* dst = (__nv_bfloat162*)(g_wb + (size_t)c * DDIM);
    if (c >= CDIM) {   // zero padding rows (masked in epilogue)
        __nv_bfloat162 z = __floats2bfloat162_rn(0.f, 0.f);
        dst[tid * 2 + 0] = z;
        dst[tid * 2 + 1] = z;
        return;
    }
    float4 v = ((const float4*)(wt + (size_t)c * DDIM))[tid];
    float ss = v.x*v.x + v.y*v.y + v.z*v.z + v.w*v.w;
    #pragma unroll
    for (int o = 16; o; o >>= 1) ss += __shfl_xor_sync(0xffffffffu, ss, o);
    __shared__ float sm[4];
    if ((tid & 31) == 0) sm[tid >> 5] = ss;
    __syncthreads();
    float tot = sm[0] + sm[1] + sm[2] + sm[3];
    float r = 1.0f / fmaxf(sqrtf(tot), 1e-12f);
    dst[tid * 2 + 0] = __floats2bfloat162_rn(v.x*r, v.y*r);
    dst[tid * 2 + 1] = __floats2bfloat162_rn(v.z*r, v.w*r);
}

__global__ void __launch_bounds__(128) cosgt_kernel(const void* __restrict__ gt,
                                                    const float* __restrict__ wt) {
    int b = blockIdx.x, tid = threadIdx.x;
    long long c = g_is64 ? ((const long long*)gt)[b] : (long long)((const int*)gt)[b];
    float4 w  = ((const float4*)(wt + (size_t)c * DDIM))[tid];
    float4 xn = ((const float4*)(g_xn + (size_t)b * DDIM))[tid];
    float ss = w.x*w.x + w.y*w.y + w.z*w.z + w.w*w.w;
    float dp = w.x*xn.x + w.y*xn.y + w.z*xn.z + w.w*xn.w;
    #pragma unroll
    for (int o = 16; o; o >>= 1) {
        ss += __shfl_xor_sync(0xffffffffu, ss, o);
        dp += __shfl_xor_sync(0xffffffffu, dp, o);
    }
    __shared__ float sms[4], smd[4];
    if ((tid & 31) == 0) { sms[tid >> 5] = ss; smd[tid >> 5] = dp; }
    __syncthreads();
    if (tid == 0) {
        float tss = sms[0] + sms[1] + sms[2] + sms[3];
        float tdp = smd[0] + smd[1] + smd[2] + smd[3];
        g_cosgt[b] = tdp / fmaxf(sqrtf(tss), 1e-12f);
    }
}

// ---------------- HMMA GEMM + fused softmax partials ----------------
// grid (37, 4), 256 threads, 8 warps (2m x 4n), warp tile 64x32.
// A [128 x 512] bf16 persistent in SMEM; B double-buffered cp.async stages.
__global__ void __launch_bounds__(256, 1) gemm_softmax_kernel() {
    extern __shared__ char smem[];
    unsigned sbase = smem_u32(smem);
    unsigned sbA = sbase;
    unsigned sbB = sbase + OFF_B;
    float (*red)[4] = (float(*)[4])(smem + OFF_RED);

    int tid  = threadIdx.x;
    int lane = tid & 31;
    int warp = tid >> 5;
    int wm = warp >> 2;       // 0..1
    int wn = warp & 3;        // 0..3
    int m0 = blockIdx.y * 128;
    int bx = blockIdx.x;

    // ---- issue B prologue (nt=bx, ck=0) into buf0 ----
    int seg = tid & 7;        // 16B segment within 128B chunk-row
    int rb  = tid >> 3;       // 0..31
    {
        const char* src = (const char*)g_wb + (size_t)(bx * TILE_N) * 1024 + seg * 16;
        #pragma unroll
        for (int q = 0; q < 4; q++) {
            int row = rb + q * 32;
            CP_ASYNC16(sbB + row * BSTRIDE_B + seg * 16, src + (size_t)row * 1024);
        }
        CP_COMMIT();
    }

    // ---- stage A[128x512] into SMEM (once) ----
    {
        #pragma unroll
        for (int it = 0; it < 32; it++) {
            int idx = it * 256 + tid;
            int r = idx >> 6, s = idx & 63;
            uint4 v = *(const uint4*)(g_xb + (size_t)(m0 + r) * DDIM + s * 8);
            *(uint4*)(smem + r * ASTRIDE_B + s * 16) = v;
        }
    }

    int g4 = lane >> 2, t4 = lane & 3;

    #pragma unroll 1
    for (int nt = bx; nt < NT; nt += GRIDX) {
        float acc[4][4][4];
        #pragma unroll
        for (int i = 0; i < 4; i++)
            #pragma unroll
            for (int j = 0; j < 4; j++)
                #pragma unroll
                for (int e = 0; e < 4; e++) acc[i][j][e] = 0.0f;

        const char* bsrc = (const char*)g_wb + (size_t)(nt * TILE_N) * 1024 + seg * 16;

        #pragma unroll 1
        for (int ck = 0; ck < 8; ck++) {
            if (ck < 7) {   // prefetch next chunk into other buffer
                int nb = (ck + 1) & 1;
                #pragma unroll
                for (int q = 0; q < 4; q++) {
                    int row = rb + q * 32;
                    CP_ASYNC16(sbB + nb * B_STAGE_BYTES + row * BSTRIDE_B + seg * 16,
                               bsrc + (size_t)row * 1024 + (ck + 1) * 128);
                }
                CP_COMMIT();
                CP_WAIT1();
            } else {
                CP_WAIT0();
            }
            __syncthreads();

            unsigned bB = sbB + (ck & 1) * B_STAGE_BYTES;
            #pragma unroll
            for (int k16 = 0; k16 < 4; k16++) {
                unsigned a[4][4];
                #pragma unroll
                for (int i = 0; i < 4; i++) {
                    int r   = wm * 64 + i * 16 + (lane & 15);
                    int col = k16 * 16 + ((lane >> 4) << 3);
                    unsigned addr = sbA + r * ASTRIDE_B + col * 2;
                    asm volatile("ldmatrix.sync.aligned.m8n8.x4.shared.b16 {%0,%1,%2,%3}, [%4];"
                                 : "=r"(a[i][0]), "=r"(a[i][1]), "=r"(a[i][2]), "=r"(a[i][3])
                                 : "r"(addr));
                }
                unsigned bfr[4][2];
                #pragma unroll
                for (int j2 = 0; j2 < 2; j2++) {
                    int nrow = wn * 32 + j2 * 16 + (lane & 7) + ((lane >> 4) << 3);
                    int col  = k16 * 16 + (((lane >> 3) & 1) << 3);
                    unsigned addr = bB + nrow * BSTRIDE_B + col * 2;
                    unsigned r0, r1, r2, r3;
                    asm volatile("ldmatrix.sync.aligned.m8n8.x4.shared.b16 {%0,%1,%2,%3}, [%4];"
                                 : "=r"(r0), "=r"(r1), "=r"(r2), "=r"(r3) : "r"(addr));
                    bfr[j2 * 2 + 0][0] = r0; bfr[j2 * 2 + 0][1] = r1;
                    bfr[j2 * 2 + 1][0] = r2; bfr[j2 * 2 + 1][1] = r3;
                }
                #pragma unroll
                for (int i = 0; i < 4; i++)
                    #pragma unroll
                    for (int j = 0; j < 4; j++)
                        asm volatile(
                            "mma.sync.aligned.m16n8k16.row.col.f32.bf16.bf16.f32 "
                            "{%0,%1,%2,%3},{%4,%5,%6,%7},{%8,%9},{%0,%1,%2,%3};"
                            : "+f"(acc[i][j][0]), "+f"(acc[i][j][1]),
                              "+f"(acc[i][j][2]), "+f"(acc[i][j][3])
                            : "r"(a[i][0]), "r"(a[i][1]), "r"(a[i][2]), "r"(a[i][3]),
                              "r"(bfr[j][0]), "r"(bfr[j][1]));
            }
            __syncthreads();
        }

        // prefetch next tile's chunk 0 into buf0 (overlaps epilogue)
        if (nt + GRIDX < NT) {
            const char* src2 = (const char*)g_wb + (size_t)((nt + GRIDX) * TILE_N) * 1024 + seg * 16;
            #pragma unroll
            for (int q = 0; q < 4; q++) {
                int row = rb + q * 32;
                CP_ASYNC16(sbB + row * BSTRIDE_B + seg * 16, src2 + (size_t)row * 1024);
            }
            CP_COMMIT();
        }

        // ---- epilogue: per-row (max, sumexp) over this 128-col tile ----
        int n0 = nt * TILE_N;
        float rmax[8];
        #pragma unroll
        for (int i = 0; i < 4; i++) {
            #pragma unroll
            for (int h = 0; h < 2; h++) {
                float m = -INFINITY;
                #pragma unroll
                for (int j = 0; j < 4; j++) {
                    #pragma unroll
                    for (int e2 = 0; e2 < 2; e2++) {
                        int gc = n0 + wn * 32 + j * 8 + t4 * 2 + e2;
                        float z = (gc < CDIM) ? SCALE_F * acc[i][j][h * 2 + e2] : -INFINITY;
                        m = fmaxf(m, z);
                    }
                }
                m = fmaxf(m, __shfl_xor_sync(0xffffffffu, m, 1));
                m = fmaxf(m, __shfl_xor_sync(0xffffffffu, m, 2));
                rmax[i * 2 + h] = m;
            }
        }
        if (t4 == 0) {
            #pragma unroll
            for (int i = 0; i < 4; i++)
                #pragma unroll
                for (int h = 0; h < 2; h++)
                    red[wm * 64 + i * 16 + h * 8 + g4][wn] = rmax[i * 2 + h];
        }
        __syncthreads();
        float fmx[8];
        #pragma unroll
        for (int i = 0; i < 4; i++)
            #pragma unroll
            for (int h = 0; h < 2; h++) {
                int r = wm * 64 + i * 16 + h * 8 + g4;
                fmx[i * 2 + h] = fmaxf(fmaxf(red[r][0], red[r][1]),
                                       fmaxf(red[r][2], red[r][3]));
            }
        __syncthreads();

        float rsum[8];
        #pragma unroll
        for (int i = 0; i < 4; i++) {
            #pragma unroll
            for (int h = 0; h < 2; h++) {
                float s = 0.0f;
                #pragma unroll
                for (int j = 0; j < 4; j++) {
                    #pragma unroll
                    for (int e2 = 0; e2 < 2; e2++) {
                        int gc = n0 + wn * 32 + j * 8 + t4 * 2 + e2;
                        if (gc < CDIM)
                            s += __expf(SCALE_F * acc[i][j][h * 2 + e2] - fmx[i * 2 + h]);
                    }
                }
                s += __shfl_xor_sync(0xffffffffu, s, 1);
                s += __shfl_xor_sync(0xffffffffu, s, 2);
                rsum[i * 2 + h] = s;
            }
        }
        if (t4 == 0) {
            #pragma unroll
            for (int i = 0; i < 4; i++)
                #pragma unroll
                for (int h = 0; h < 2; h++)
                    red[wm * 64 + i * 16 + h * 8 + g4][wn] = rsum[i * 2 + h];
        }
        __syncthreads();
        if (wn == 0 && t4 == 0) {
            #pragma unroll
            for (int i = 0; i < 4; i++)
                #pragma unroll
                for (int h = 0; h < 2; h++) {
                    int r = wm * 64 + i * 16 + h * 8 + g4;
                    float S = red[r][0] + red[r][1] + red[r][2] + red[r][3];
                    g_pm[(m0 + r) * NCHUNK + nt] = fmx[i * 2 + h];
                    g_ps[(m0 + r) * NCHUNK + nt] = S;
                }
        }
        __syncthreads();
    }
}

// ---------------- logsumexp merge + margin + NLL ----------------
__global__ void __launch_bounds__(256) reduce_kernel() {
    int b = blockIdx.x, tid = threadIdx.x;
    float M = -INFINITY, S = 0.0f;
    for (int i = tid; i < NCHUNK; i += 256) {
        float m = g_pm[b * NCHUNK + i];
        float s = g_ps[b * NCHUNK + i];
        if (m > M) { S = S * expf(M - m) + s; M = m; }
        else       { S += s * expf(m - M); }
    }
    __shared__ float sm[256], ss[256];
    sm[tid] = M; ss[tid] = S;
    __syncthreads();
    for (int o = 128; o; o >>= 1) {
        if (tid < o) {
            float m2 = sm[tid + o], s2 = ss[tid + o];
            float m1 = sm[tid],     s1 = ss[tid];
            float mn = fmaxf(m1, m2);
            sm[tid] = mn;
            ss[tid] = s1 * expf(m1 - mn) + s2 * expf(m2 - mn);
        }
        __syncthreads();
    }
    if (tid == 0) {
        float Mf = sm[0], Sf = ss[0];
        float zg = SCALE_F * g_cosgt[b];
        float zm = zg - SCALE_F * MARGIN_F;
        Sf = Sf - expf(zg - Mf) + expf(zm - Mf);
        float lse = Mf + logf(Sf);
        g_nll[b] = lse - zm;
    }
}

__global__ void __launch_bounds__(512) mean_kernel(float* __restrict__ out) {
    __shared__ float sm[512];
    int t = threadIdx.x;
    sm[t] = g_nll[t];
    __syncthreads();
    for (int o = 256; o; o >>= 1) {
        if (t < o) sm[t] += sm[t + o];
        __syncthreads();
    }
    if (t == 0) out[0] = sm[0] * (1.0f / (float)BDIM);
}

// ---------------- launch ----------------
extern "C" void kernel_launch(void* const* d_in, const int* in_sizes, int n_in,
                              void* d_out, int out_size) {
    const float* x  = (const float*)d_in[0];
    const void*  gt = d_in[1];
    const float* wt = (const float*)d_in[2];
    float* out = (float*)d_out;

    static int smem_set = 0;
    if (!smem_set) {
        cudaFuncSetAttribute(gemm_softmax_kernel,
                             cudaFuncAttributeMaxDynamicSharedMemorySize, SMEM_DYN);
        smem_set = 1;
    }

    detect_gt_kernel<<<1, 512>>>((const int*)gt);
    norm_x_kernel<<<BDIM, 128>>>(x);
    norm_w_kernel<<<C_PAD, 128>>>(wt);
    cosgt_kernel<<<BDIM, 128>>>(gt, wt);
    gemm_softmax_kernel<<<dim3(GRIDX, 4), 256, SMEM_DYN>>>();
    reduce_kernel<<<BDIM, 256>>>();
    mean_kernel<<<1, 512>>>(out);
}